// round 6
// baseline (speedup 1.0000x reference)
#include <cuda_runtime.h>
#include <cuda_bf16.h>

// ConeProjection: out[b,k] = P[k]^T * sigma[b] * P[k]
//   sigma[a][c] = (vn·w_a)(vn·w_c) - alpha*(w_a·w_c)
//   w0 = R[:,0], w1 = R[:,1], w2 = t - eyes, vn = v/max(||v||,1e-14)
//   P[k] = ((ki-6)/6, (kj-6)/6, 1),  k = 13*ki + kj
//
// out is quadratic: per (b, ki) row, out = A + B*y + C*y^2, y=(kj-6)/6.
// Prologue: 208 threads (one per (batch,row)) redundantly build coefficients
// and write (A,B,C) float4 rows to smem. One __syncthreads. Main loop: direct
// STG.128 of output float4s, each element decoded with exact magic divides
// and evaluated with 2 FFMA from an LDS.128 row fetch. No staging buffer.

#define K_GRID   169
#define GROUP    16
#define THREADS  256
#define ELEMS    (GROUP * K_GRID)   // 2704
#define NVEC     (ELEMS / 4)        // 676
#define NROWS    (GROUP * 13)       // 208

__global__ __launch_bounds__(THREADS, 8)
void cone_projection_kernel(const float* __restrict__ eyes,
                            const float* __restrict__ v,
                            const float* __restrict__ R,
                            const float* __restrict__ t,
                            const float* __restrict__ alpha,
                            float* __restrict__ out,
                            int B)
{
    __shared__ float4 rowc[NROWS];   // (A, B, C, unused) per (batch, ki)

    const int tid = threadIdx.x;
    const long long base_b = (long long)blockIdx.x * GROUP;

    // --- Prologue: one thread per (batch, ki) row; redundant coeff compute ---
    if (tid < NROWS) {
        const int bl = (tid * 158) >> 11;   // tid/13, exact for tid<208
        const int ki = tid - 13 * bl;
        const long long b = base_b + bl;

        if (b < B) {
            float vx = v[b * 3 + 0];
            float vy = v[b * 3 + 1];
            float vz = v[b * 3 + 2];
            float n  = fmaxf(sqrtf(vx * vx + vy * vy + vz * vz), 1e-14f);
            float inv = 1.0f / n;
            vx *= inv; vy *= inv; vz *= inv;

            const float a = alpha[b];

            const float* Rb = R + b * 9;
            const float w0x = Rb[0], w0y = Rb[3], w0z = Rb[6];   // R[:,0]
            const float w1x = Rb[1], w1y = Rb[4], w1z = Rb[7];   // R[:,1]
            const float w2x = t[b * 3 + 0] - eyes[b * 3 + 0];
            const float w2y = t[b * 3 + 1] - eyes[b * 3 + 1];
            const float w2z = t[b * 3 + 2] - eyes[b * 3 + 2];

            const float d0 = vx * w0x + vy * w0y + vz * w0z;
            const float d1 = vx * w1x + vy * w1y + vz * w1z;
            const float d2 = vx * w2x + vy * w2y + vz * w2z;

            const float c0 = d0 * d0 - a * (w0x * w0x + w0y * w0y + w0z * w0z); // x^2
            const float c1 = d1 * d1 - a * (w1x * w1x + w1y * w1y + w1z * w1z); // y^2
            const float c2 = d2 * d2 - a * (w2x * w2x + w2y * w2y + w2z * w2z); // 1
            const float c3 = 2.0f * (d0 * d1 - a * (w0x * w1x + w0y * w1y + w0z * w1z)); // xy
            const float c4 = 2.0f * (d0 * d2 - a * (w0x * w2x + w0y * w2y + w0z * w2z)); // x
            const float c5 = 2.0f * (d1 * d2 - a * (w1x * w2x + w1y * w2y + w1z * w2z)); // y

            const float x  = (float)(ki - 6) * (1.0f / 6.0f);
            const float A  = fmaf(fmaf(c0, x, c4), x, c2);  // c2 + c4 x + c0 x^2
            const float Bq = fmaf(c3, x, c5);               // c5 + c3 x
            rowc[tid] = make_float4(A, Bq, c1, 0.0f);
        }
    }
    __syncthreads();

    // --- Main loop: direct coalesced float4 stores ---
    const long long rem = (long long)B - base_b;
    float* outp = out + base_b * K_GRID;

    if (rem >= GROUP) {
        float4* out4 = reinterpret_cast<float4*>(outp);
        #pragma unroll
        for (int i = tid; i < NVEC; i += THREADS) {
            const int f0 = i * 4;
            float r[4];
            #pragma unroll
            for (int e = 0; e < 4; ++e) {
                const int f  = f0 + e;
                const int bl = (f * 6205) >> 20;          // f/169, exact f<2704
                const int k  = f - 169 * bl;
                const int ki = (k * 79) >> 10;            // k/13, exact k<169
                const int kj = k - 13 * ki;
                const float4 c = rowc[bl * 13 + ki];
                const float y = (float)(kj - 6) * (1.0f / 6.0f);
                r[e] = fmaf(fmaf(c.z, y, c.y), y, c.x);   // A + B y + C y^2
            }
            out4[i] = make_float4(r[0], r[1], r[2], r[3]);
        }
    } else {
        // tail block: rem*169 valid floats, scalar-guarded
        const int nval = (int)rem * K_GRID;
        for (int f = tid; f < nval; f += THREADS) {
            const int bl = (f * 6205) >> 20;
            const int k  = f - 169 * bl;
            const int ki = (k * 79) >> 10;
            const int kj = k - 13 * ki;
            const float4 c = rowc[bl * 13 + ki];
            const float y = (float)(kj - 6) * (1.0f / 6.0f);
            outp[f] = fmaf(fmaf(c.z, y, c.y), y, c.x);
        }
    }
}

extern "C" void kernel_launch(void* const* d_in, const int* in_sizes, int n_in,
                              void* d_out, int out_size) {
    const float* eyes  = (const float*)d_in[0];
    const float* v     = (const float*)d_in[1];
    const float* R     = (const float*)d_in[2];
    const float* t     = (const float*)d_in[3];
    const float* alpha = (const float*)d_in[4];
    float* out = (float*)d_out;

    const int B = in_sizes[4];                    // alpha: B elements
    const int blocks = (B + GROUP - 1) / GROUP;   // 8192 for B=131072

    cone_projection_kernel<<<blocks, THREADS>>>(eyes, v, R, t, alpha, out, B);
}

// round 7
// speedup vs baseline: 1.4277x; 1.4277x over previous
#include <cuda_runtime.h>
#include <cuda_bf16.h>

// ConeProjection: out[b,k] = P[k]^T * sigma[b] * P[k]
//   sigma[a][c] = (vn·w_a)(vn·w_c) - alpha*(w_a·w_c)
//   w0 = R[:,0], w1 = R[:,1], w2 = t - eyes, vn = v/max(||v||,1e-14)
//   P[k] = ((ki-6)/6, (kj-6)/6, 1),  k = 13*ki + kj
//
// Layout: one warp owns NB=16 batches. Lanes 0..15 compute the 6 quadratic
// coefficients (phase A) into smem; __syncwarp; phase B iterates the 16
// batches, reading coeffs via broadcast LDS.128 and emitting 169 outputs as
// 6 coalesced STG passes (k = lane + 32p), 5 FFMA each, with the per-thread
// grid geometry (x^2, y^2, xy, x, y for all 6 passes) precomputed in regs.
// No block barriers, no per-element decode, no per-element shared loads.

#define K_GRID  169
#define NB      16            // batches per warp
#define WARPS   8             // warps per block
#define THREADS (WARPS * 32)

__global__ __launch_bounds__(THREADS)
void cone_projection_kernel(const float* __restrict__ eyes,
                            const float* __restrict__ v,
                            const float* __restrict__ R,
                            const float* __restrict__ t,
                            const float* __restrict__ alpha,
                            float* __restrict__ out,
                            int B)
{
    __shared__ float4 scoef[WARPS * NB * 2];   // per batch: (c0,c1,c2,c3),(c4,c5,-,-)

    const int lane = threadIdx.x & 31;
    const int wid  = threadIdx.x >> 5;
    const long long base_b = ((long long)blockIdx.x * WARPS + wid) * NB;

    // --- Per-thread grid geometry for k = lane + 32p, p = 0..5 (registers) ---
    float gx2[6], gy2[6], gxy[6], gx[6], gy[6];
    #pragma unroll
    for (int p = 0; p < 6; ++p) {
        const int k  = lane + 32 * p;
        const int ki = (k * 79) >> 10;          // k/13, exact for k < 169
        const int kj = k - 13 * ki;
        const float x = (float)(ki - 6) * (1.0f / 6.0f);
        const float y = (float)(kj - 6) * (1.0f / 6.0f);
        gx2[p] = x * x;  gy2[p] = y * y;  gxy[p] = x * y;
        gx[p]  = x;      gy[p]  = y;
    }

    // --- Phase A: lanes 0..15 build coefficients for their batch ---
    if (lane < NB) {
        const long long b = base_b + lane;
        if (b < B) {
            float vx = v[b * 3 + 0];
            float vy = v[b * 3 + 1];
            float vz = v[b * 3 + 2];
            float n  = fmaxf(sqrtf(vx * vx + vy * vy + vz * vz), 1e-14f);
            float inv = 1.0f / n;
            vx *= inv; vy *= inv; vz *= inv;

            const float a = alpha[b];

            const float* Rb = R + b * 9;
            const float w0x = Rb[0], w0y = Rb[3], w0z = Rb[6];   // R[:,0]
            const float w1x = Rb[1], w1y = Rb[4], w1z = Rb[7];   // R[:,1]
            const float w2x = t[b * 3 + 0] - eyes[b * 3 + 0];
            const float w2y = t[b * 3 + 1] - eyes[b * 3 + 1];
            const float w2z = t[b * 3 + 2] - eyes[b * 3 + 2];

            const float d0 = vx * w0x + vy * w0y + vz * w0z;
            const float d1 = vx * w1x + vy * w1y + vz * w1z;
            const float d2 = vx * w2x + vy * w2y + vz * w2z;

            const float c0 = d0 * d0 - a * (w0x * w0x + w0y * w0y + w0z * w0z); // x^2
            const float c1 = d1 * d1 - a * (w1x * w1x + w1y * w1y + w1z * w1z); // y^2
            const float c2 = d2 * d2 - a * (w2x * w2x + w2y * w2y + w2z * w2z); // 1
            const float c3 = 2.0f * (d0 * d1 - a * (w0x * w1x + w0y * w1y + w0z * w1z)); // xy
            const float c4 = 2.0f * (d0 * d2 - a * (w0x * w2x + w0y * w2y + w0z * w2z)); // x
            const float c5 = 2.0f * (d1 * d2 - a * (w1x * w2x + w1y * w2y + w1z * w2z)); // y

            const int s = (wid * NB + lane) * 2;
            scoef[s]     = make_float4(c0, c1, c2, c3);
            scoef[s + 1] = make_float4(c4, c5, 0.0f, 0.0f);
        }
    }
    __syncwarp();

    // --- Phase B: 16 batches x (2 broadcast LDS.128 + 6 x (5 FFMA + STG)) ---
    #pragma unroll 4
    for (int bt = 0; bt < NB; ++bt) {
        const long long b = base_b + bt;
        if (b >= B) break;

        const int s = (wid * NB + bt) * 2;
        const float4 ca = scoef[s];       // c0 c1 c2 c3
        const float4 cb = scoef[s + 1];   // c4 c5 -  -

        float* o = out + b * (long long)K_GRID + lane;

        #pragma unroll
        for (int p = 0; p < 6; ++p) {
            float r = fmaf(ca.x, gx2[p], ca.z);
            r = fmaf(ca.y, gy2[p], r);
            r = fmaf(ca.w, gxy[p], r);
            r = fmaf(cb.x, gx[p],  r);
            r = fmaf(cb.y, gy[p],  r);
            if (p < 5 || lane < K_GRID - 160)   // last pass: k=160+lane < 169
                o[p * 32] = r;
        }
    }
}

extern "C" void kernel_launch(void* const* d_in, const int* in_sizes, int n_in,
                              void* d_out, int out_size) {
    const float* eyes  = (const float*)d_in[0];
    const float* v     = (const float*)d_in[1];
    const float* R     = (const float*)d_in[2];
    const float* t     = (const float*)d_in[3];
    const float* alpha = (const float*)d_in[4];
    float* out = (float*)d_out;

    const int B = in_sizes[4];                           // alpha: B elements
    const int warp_groups = (B + NB - 1) / NB;           // 8192 for B=131072
    const int blocks = (warp_groups + WARPS - 1) / WARPS; // 1024

    cone_projection_kernel<<<blocks, THREADS>>>(eyes, v, R, t, alpha, out, B);
}

// round 8
// speedup vs baseline: 1.5300x; 1.0717x over previous
#include <cuda_runtime.h>
#include <cuda_bf16.h>

// ConeProjection: out[b,k] = P[k]^T * sigma[b] * P[k]
//   sigma[a][c] = (vn·w_a)(vn·w_c) - alpha*(w_a·w_c)
//   w0 = R[:,0], w1 = R[:,1], w2 = t - eyes, vn = v/max(||v||,1e-14)
//   P[k] = ((ki-6)/6, (kj-6)/6, 1),  k = 13*ki + kj
//
// Warp owns NB=16 batches. Lanes 0..15 build the 6 quadratic coefficients
// into smem (__syncwarp only). Phase B: per batch, 2 broadcast LDS.128 then
// 6 coalesced store passes (k = lane + 32p), 5 FFMA each using only the
// per-thread grid coords x[p], y[p] (12 regs total -> low reg pressure,
// high occupancy). Streaming stores (evict-first) for the write-once output.

#define K_GRID  169
#define NB      16            // batches per warp
#define WARPS   8             // warps per block
#define THREADS (WARPS * 32)

__global__ __launch_bounds__(THREADS, 6)
void cone_projection_kernel(const float* __restrict__ eyes,
                            const float* __restrict__ v,
                            const float* __restrict__ R,
                            const float* __restrict__ t,
                            const float* __restrict__ alpha,
                            float* __restrict__ out,
                            int B)
{
    __shared__ float4 scoef[WARPS * NB * 2];   // per batch: (c0,c1,c2,c3),(c4,c5,-,-)

    const int lane = threadIdx.x & 31;
    const int wid  = threadIdx.x >> 5;
    const long long base_b = ((long long)blockIdx.x * WARPS + wid) * NB;

    // --- Per-thread grid coords for k = lane + 32p, p = 0..5 (12 registers) ---
    float xs[6], ys[6];
    #pragma unroll
    for (int p = 0; p < 6; ++p) {
        const int k  = lane + 32 * p;
        const int ki = (k * 79) >> 10;          // k/13, exact for k < 169
        const int kj = k - 13 * ki;
        xs[p] = (float)(ki - 6) * (1.0f / 6.0f);
        ys[p] = (float)(kj - 6) * (1.0f / 6.0f);
    }

    // --- Phase A: lanes 0..15 build coefficients for their batch ---
    if (lane < NB) {
        const long long b = base_b + lane;
        if (b < B) {
            float vx = v[b * 3 + 0];
            float vy = v[b * 3 + 1];
            float vz = v[b * 3 + 2];
            float n  = fmaxf(sqrtf(vx * vx + vy * vy + vz * vz), 1e-14f);
            float inv = 1.0f / n;
            vx *= inv; vy *= inv; vz *= inv;

            const float a = alpha[b];

            const float* Rb = R + b * 9;
            const float w0x = Rb[0], w0y = Rb[3], w0z = Rb[6];   // R[:,0]
            const float w1x = Rb[1], w1y = Rb[4], w1z = Rb[7];   // R[:,1]
            const float w2x = t[b * 3 + 0] - eyes[b * 3 + 0];
            const float w2y = t[b * 3 + 1] - eyes[b * 3 + 1];
            const float w2z = t[b * 3 + 2] - eyes[b * 3 + 2];

            const float d0 = vx * w0x + vy * w0y + vz * w0z;
            const float d1 = vx * w1x + vy * w1y + vz * w1z;
            const float d2 = vx * w2x + vy * w2y + vz * w2z;

            const float c0 = d0 * d0 - a * (w0x * w0x + w0y * w0y + w0z * w0z); // x^2
            const float c1 = d1 * d1 - a * (w1x * w1x + w1y * w1y + w1z * w1z); // y^2
            const float c2 = d2 * d2 - a * (w2x * w2x + w2y * w2y + w2z * w2z); // 1
            const float c3 = 2.0f * (d0 * d1 - a * (w0x * w1x + w0y * w1y + w0z * w1z)); // xy
            const float c4 = 2.0f * (d0 * d2 - a * (w0x * w2x + w0y * w2y + w0z * w2z)); // x
            const float c5 = 2.0f * (d1 * d2 - a * (w1x * w2x + w1y * w2y + w1z * w2z)); // y

            const int s = (wid * NB + lane) * 2;
            scoef[s]     = make_float4(c0, c1, c2, c3);
            scoef[s + 1] = make_float4(c4, c5, 0.0f, 0.0f);
        }
    }
    __syncwarp();

    // --- Phase B: 16 batches x (2 broadcast LDS.128 + 6 x (5 FFMA + STG)) ---
    #pragma unroll 4
    for (int bt = 0; bt < NB; ++bt) {
        const long long b = base_b + bt;
        if (b >= B) break;

        const int s = (wid * NB + bt) * 2;
        const float4 ca = scoef[s];       // c0 c1 c2 c3
        const float4 cb = scoef[s + 1];   // c4 c5 -  -

        float* o = out + b * (long long)K_GRID + lane;

        #pragma unroll
        for (int p = 0; p < 6; ++p) {
            const float x = xs[p];
            const float y = ys[p];
            // r = x*(c0*x + c4) + y*(c1*y + c3*x + c5) + c2   (5 FFMA)
            const float t1 = fmaf(ca.x, x, cb.x);
            float       t2 = fmaf(ca.y, y, cb.y);
            t2 = fmaf(ca.w, x, t2);
            float r  = fmaf(x, t1, ca.z);
            r = fmaf(y, t2, r);
            if (p < 5 || lane < K_GRID - 160)   // last pass: k = 160+lane < 169
                __stcs(&o[p * 32], r);          // streaming (evict-first) store
        }
    }
}

extern "C" void kernel_launch(void* const* d_in, const int* in_sizes, int n_in,
                              void* d_out, int out_size) {
    const float* eyes  = (const float*)d_in[0];
    const float* v     = (const float*)d_in[1];
    const float* R     = (const float*)d_in[2];
    const float* t     = (const float*)d_in[3];
    const float* alpha = (const float*)d_in[4];
    float* out = (float*)d_out;

    const int B = in_sizes[4];                            // alpha: B elements
    const int warp_groups = (B + NB - 1) / NB;            // 8192 for B=131072
    const int blocks = (warp_groups + WARPS - 1) / WARPS; // 1024

    cone_projection_kernel<<<blocks, THREADS>>>(eyes, v, R, t, alpha, out, B);
}